// round 10
// baseline (speedup 1.0000x reference)
#include <cuda_runtime.h>

#define N_POS   1024
#define BDIM    512
#define SPLIT   4
#define NBLK    (64 * SPLIT)   // 256
#define KTOP    10
#define NWARP   (BDIM / 32)    // 16
#define LSIZE   (N_POS + 128)  // list capacity incl. zero pad (float2 entries)

__device__ float    g_partial[NBLK];
__device__ int      g_count[NBLK];
__device__ unsigned g_ticket;   // zero-init; reset to 0 by the last block each launch

__constant__ float c_idcg[11] = {
    0.0f, 1.0f, 1.6309297535714574f, 2.1309297535714574f,
    2.5616063116448505f, 2.9484591188793920f, 3.3046663059874144f,
    3.6379996393207477f, 3.9534645161064764f, 4.2544945117704580f,
    4.5435593380883460f
};

__global__ __launch_bounds__(BDIM, 2) void lambdarank_fused(
    const float* __restrict__ scores, const int* __restrict__ rels,
    float* __restrict__ out)
{
    __shared__ float4 relSD4[LSIZE / 2];   // (E, d) pairs, float4 view
    __shared__ float4 nonSD4[LSIZE / 2];
    __shared__ int    sh_cntR[NWARP];
    __shared__ int    sh_baseR[NWARP], sh_baseN[NWARP];
    __shared__ int    sh_tot[2];
    __shared__ float  red_f[NWARP];
    __shared__ int    red_i[NWARP];
    __shared__ bool   s_last;

    float2* relSD = (float2*)relSD4;
    float2* nonSD = (float2*)nonSD4;

    const int b    = blockIdx.x >> 2;          // SPLIT = 4
    const int s    = blockIdx.x & (SPLIT - 1);
    const int t    = threadIdx.x;
    const int lane = t & 31;
    const int wid  = t >> 5;
    const unsigned lt_mask = (1u << lane) - 1u;

    // ---- Parallel deterministic stable compaction (16 warps, 64 pos each) ----
    unsigned masks[2];
    float    sc[2];
    {
        int cr = 0;
        #pragma unroll
        for (int it = 0; it < 2; it++) {
            int p = (wid << 6) + (it << 5) + lane;
            sc[it] = scores[b * N_POS + p];
            int r  = rels[b * N_POS + p];
            unsigned m = __ballot_sync(0xffffffffu, r != 0);
            masks[it] = m;
            cr += __popc(m);
        }
        if (lane == 0) sh_cntR[wid] = cr;
    }
    __syncthreads();
    if (t == 0) {
        int aR = 0, aN = 0;
        #pragma unroll
        for (int w = 0; w < NWARP; w++) {
            sh_baseR[w] = aR; sh_baseN[w] = aN;
            aR += sh_cntR[w]; aN += 64 - sh_cntR[w];
        }
        sh_tot[0] = aR; sh_tot[1] = aN;
    }
    __syncthreads();

    const int nrel = sh_tot[0];
    const int nnon = sh_tot[1];

    {
        int rb = sh_baseR[wid], nb = sh_baseN[wid];
        #pragma unroll
        for (int it = 0; it < 2; it++) {
            int p = (wid << 6) + (it << 5) + lane;
            unsigned m = masks[it];
            bool hit = (m >> lane) & 1u;
            float E  = __expf(hit ? -sc[it] : sc[it]);                 // 1 MUFU
            float d  = __fdividef(1.0f, __log2f((float)p + 2.0f));     // 2 MUFU
            float2 v = make_float2(E, d);
            int preR = __popc(m & lt_mask);
            if (hit) relSD[rb + preR]          = v;
            else     nonSD[nb + (lane - preR)] = v;
            rb += __popc(m);
            nb += 32 - __popc(m);
        }
    }

    // Zero-fill tails: E=0 entries contribute exactly 0 in the pair loop
    for (int idx = nrel + t; idx < LSIZE; idx += BDIM)
        relSD[idx] = make_float2(0.0f, 0.0f);
    for (int idx = nnon + t; idx < LSIZE; idx += BDIM)
        nonSD[idx] = make_float2(0.0f, 0.0f);
    __syncthreads();

    float thread_sum = 0.0f;
    int   blk_count  = 0;

    if (nrel > 0 && nnon > 0) {
        const float idcg = c_idcg[(nrel < KTOP) ? nrel : KTOP];
        const float norm = 0.69314718055994531f / (idcg + 1e-8f);  // ln2/(idcg+eps)

        const int chunk = (((nnon + SPLIT - 1) >> 2) + 7) & ~7;
        const int j0    = s * chunk;
        int cntj  = nnon - j0;
        cntj  = (cntj < 0) ? 0 : ((cntj > chunk) ? chunk : cntj);
        blk_count = nrel * cntj;

        // float4 steps (2 j's each), rounded to multiple of 2; overread -> zero-pad
        const int trips4 = (((cntj + 1) >> 1) + 1) & ~1;
        const float4* nj4 = (const float4*)&nonSD[j0];

        // 4 i's per thread: i = 4t .. 4t+3 covers up to 2048 >= nrel (single pass).
        // Whole-warp skip at 128-i granularity; zero-pad covers partial warps.
        if (trips4 > 0 && (wid << 7) < nrel) {
            const float4 rv0 = relSD4[2 * t];
            const float4 rv1 = relSD4[2 * t + 1];
            const float Ei0 = rv0.x, di0 = rv0.y;
            const float Ei1 = rv0.z, di1 = rv0.w;
            const float Ei2 = rv1.x, di2 = rv1.y;
            const float Ei3 = rv1.z, di3 = rv1.w;

            float a0 = 0.0f, a1 = 0.0f, a2 = 0.0f, a3 = 0.0f;
            #pragma unroll 2
            for (int k = 0; k < trips4; k++) {
                const float4 n = nj4[k];                 // 2 j's per LDS.128 (broadcast)
                // j = (n.x, n.y): 4 pairs, 4 ops each
                a0 = fmaf(fabsf(di0 - n.y), __log2f(fmaf(n.x, Ei0, 1.0f)), a0);
                a1 = fmaf(fabsf(di1 - n.y), __log2f(fmaf(n.x, Ei1, 1.0f)), a1);
                a2 = fmaf(fabsf(di2 - n.y), __log2f(fmaf(n.x, Ei2, 1.0f)), a2);
                a3 = fmaf(fabsf(di3 - n.y), __log2f(fmaf(n.x, Ei3, 1.0f)), a3);
                // j = (n.z, n.w): 4 pairs
                a0 = fmaf(fabsf(di0 - n.w), __log2f(fmaf(n.z, Ei0, 1.0f)), a0);
                a1 = fmaf(fabsf(di1 - n.w), __log2f(fmaf(n.z, Ei1, 1.0f)), a1);
                a2 = fmaf(fabsf(di2 - n.w), __log2f(fmaf(n.z, Ei2, 1.0f)), a2);
                a3 = fmaf(fabsf(di3 - n.w), __log2f(fmaf(n.z, Ei3, 1.0f)), a3);
            }
            thread_sum = ((a0 + a1) + (a2 + a3)) * norm;
        }
    }

    // ---- Deterministic block reduction (16 warps) ----
    {
        float ws = thread_sum;
        #pragma unroll
        for (int o = 16; o > 0; o >>= 1) ws += __shfl_down_sync(0xffffffffu, ws, o);
        if (lane == 0) red_f[wid] = ws;
        __syncthreads();
        if (wid == 0) {
            float v2 = (lane < NWARP) ? red_f[lane] : 0.0f;
            #pragma unroll
            for (int o = 8; o > 0; o >>= 1) v2 += __shfl_down_sync(0xffffffffu, v2, o);
            if (lane == 0) {
                g_partial[blockIdx.x] = v2;
                g_count[blockIdx.x]   = blk_count;
            }
        }
    }

    // ---- Fused finalize: last block reduces all partials in fixed order ----
    __threadfence();
    if (t == 0)
        s_last = (atomicAdd(&g_ticket, 1u) == (unsigned)(NBLK - 1));
    __syncthreads();

    if (s_last) {
        float fs = 0.0f;
        int   cs = 0;
        if (t < NBLK) {                      // NBLK = 256 < BDIM = 512
            fs = g_partial[t];
            cs = g_count[t];
        }
        #pragma unroll
        for (int o = 16; o > 0; o >>= 1) {
            fs += __shfl_down_sync(0xffffffffu, fs, o);
            cs += __shfl_down_sync(0xffffffffu, cs, o);
        }
        if (lane == 0) { red_f[wid] = fs; red_i[wid] = cs; }
        __syncthreads();
        if (t == 0) {
            float st = 0.0f; int ct = 0;
            #pragma unroll
            for (int w = 0; w < NWARP; w++) { st += red_f[w]; ct += red_i[w]; }
            out[0] = (ct > 0) ? (st / (float)ct) : 0.0f;
            g_ticket = 0;   // reset for next graph replay
        }
    }
}

extern "C" void kernel_launch(void* const* d_in, const int* in_sizes, int n_in,
                              void* d_out, int out_size)
{
    const float* scores = (const float*)d_in[0];
    const int*   rels   = (const int*)d_in[1];
    (void)in_sizes; (void)n_in; (void)out_size;

    lambdarank_fused<<<NBLK, BDIM>>>(scores, rels, (float*)d_out);
}